// round 16
// baseline (speedup 1.0000x reference)
#include <cuda_runtime.h>
#include <cstdint>

#define BN 512
#define NSTEPS 100

// ---------------- persistent device state (allocation-free scratch) ----------------
__device__ uint32_t g_spk_all[NSTEPS][BN][28];       // input spike bits, 28-bit row words
__device__ uint8_t  g_opmq[NSTEPS][BN * 196][4];     // pool1 quarter-masks (5 bits per group byte)
__device__ uint32_t g_op2m_all[NSTEPS][BN][2][40];   // pool2 spike masks per step
__device__ float    g_tf0 [BN * 200];                // fc0 total spike count (ONLY output that matters)
__device__ float    g_w1t [500];                     // w1 transposed [tap][ch]
__device__ float    g_w2t [2 * 500 * 26];            // conv2 weights [cb][kk*20+ci][ch pad26]
__device__ float    g_wf0T[2450 * 200];              // wf0 transposed [k][n]

// ---------------- Threefry-2x32, 20 rounds (matches JAX exactly) ----------------
__host__ __device__ __forceinline__ void tf2x32(uint32_t k0, uint32_t k1,
                                                uint32_t x0, uint32_t x1,
                                                uint32_t& o0, uint32_t& o1) {
    uint32_t k2 = k0 ^ k1 ^ 0x1BD11BDAu;
    x0 += k0; x1 += k1;
#define TFR(r) { x0 += x1; x1 = (x1 << (r)) | (x1 >> (32 - (r))); x1 ^= x0; }
    TFR(13) TFR(15) TFR(26) TFR(6)   x0 += k1; x1 += k2 + 1u;
    TFR(17) TFR(29) TFR(16) TFR(24)  x0 += k2; x1 += k0 + 2u;
    TFR(13) TFR(15) TFR(26) TFR(6)   x0 += k0; x1 += k1 + 3u;
    TFR(17) TFR(29) TFR(16) TFR(24)  x0 += k1; x1 += k2 + 4u;
    TFR(13) TFR(15) TFR(26) TFR(6)   x0 += k2; x1 += k0 + 5u;
#undef TFR
    o0 = x0; o1 = x1;
}

// ---------------- one-time prep: transposes ----------------
__global__ void k_prep(const float* __restrict__ w1, const float* __restrict__ w2,
                       const float* __restrict__ wf0) {
    int i = blockIdx.x * blockDim.x + threadIdx.x;
    if (i < 500) {
        int tap = i / 20, ch = i % 20;
        g_w1t[i] = w1[ch * 25 + tap];
    }
    int h = i - 500;
    if (h >= 0 && h < 2 * 500 * 26) {
        int ch = h % 26, rem = h / 26, kkci = rem % 500, cb = rem / 500;
        int kk = kkci / 20, ci = kkci % 20;
        g_w2t[h] = (ch < 25) ? w2[(cb * 25 + ch) * 500 + ci * 25 + kk] : 0.f;
    }
    int j = i - 500 - 2 * 500 * 26;
    if (j >= 0 && j < 2450 * 200) {
        int n = j % 200, k = j / 200;
        g_wf0T[j] = wf0[n * 2450 + k];
    }
}

// ---------------- RNG: ALL spike bits via warp ballot (exact threefry decisions) ----------------
// warp-task = (tt, b, row): lane ℓ<28 computes pixel (row, ℓ); ballot -> 28-bit word.
__global__ void k_rng_all(const float* __restrict__ in) {
    int gw = (blockIdx.x * blockDim.x + threadIdx.x) >> 5;
    int lane = threadIdx.x & 31;
    if (gw >= NSTEPS * BN * 28) return;
    int row = gw % 28;
    int rem = gw / 28;
    int b  = rem % BN;
    int tt = rem / BN;
    uint32_t kk0, kk1;
    tf2x32(0u, 42u, 0u, (uint32_t)tt, kk0, kk1);
    bool spike = false;
    if (lane < 28) {
        int i = row * 28 + lane;
        uint32_t o0, o1;
        tf2x32(kk0, kk1, 0u, (uint32_t)(b * 784 + i), o0, o1);
        uint32_t bits = o0 ^ o1;
        float u = __uint_as_float((bits >> 9) | 0x3f800000u) - 1.0f;
        float v = in[b * 784 + i];
        spike = (fabsf(v) * 0.5f > u) && (v != 0.0f);   // sign(v)=1 for v>0 (uniform input)
    }
    uint32_t w = __ballot_sync(0xFFFFFFFFu, spike) & 0x0FFFFFFFu;
    if (lane == 0) g_spk_all[tt][b][row] = w;
}

// ---------------- conv1, ALL steps, SPARSE: per set bit add 5 weights ----------------
// grid (b, 4 ch-groups of 5). Thread = pooled position; membranes in registers.
// Window bit order = (ky,kx) row-major = ascending chain order (bit-exact skip of zeros).
__device__ __forceinline__ uint32_t ext5(uint32_t R, int c) {
    return (c >= 2) ? ((R >> (c - 2)) & 31u) : ((R << (2 - c)) & 31u);
}
__global__ __launch_bounds__(224, 4) void k_conv1_all() {
    __shared__ float sw5[125];          // [tap][5 ch of this group]
    int b = blockIdx.x, g = blockIdx.y;
    int t = threadIdx.x;
    for (int i = t; i < 125; i += 224) sw5[i] = g_w1t[(i / 5) * 20 + g * 5 + (i % 5)];
    __syncthreads();
    if (t >= 196) return;
    int py = t / 14, px = t % 14;
    int r0 = 2 * py, c0 = 2 * px;
    float m1r[5][4];
    float m1sr[5];
#pragma unroll
    for (int c = 0; c < 5; c++) {
        m1sr[c] = 0.f;
#pragma unroll
        for (int j = 0; j < 4; j++) m1r[c][j] = 0.f;
    }
    uint8_t* outp = &g_opmq[0][b * 196 + t][g];

    for (int tt = 0; tt < NSTEPS; tt++) {
        uint32_t R[6];
#pragma unroll
        for (int j = 0; j < 6; j++) {
            int r = r0 - 2 + j;
            R[j] = (r >= 0 && r < 28) ? g_spk_all[tt][b][r] : 0u;
        }
        uint32_t e0[6], e1[6];
#pragma unroll
        for (int j = 0; j < 6; j++) { e0[j] = ext5(R[j], c0); e1[j] = ext5(R[j], c0 + 1); }
        uint32_t w00 = 0, w01 = 0, w10 = 0, w11 = 0;
#pragma unroll
        for (int ky = 0; ky < 5; ky++) {
            w00 |= e0[ky] << (5 * ky);
            w01 |= e1[ky] << (5 * ky);
            w10 |= e0[ky + 1] << (5 * ky);
            w11 |= e1[ky + 1] << (5 * ky);
        }

        float acc[5][4] = {};
        while (w00) {
            int bit = __ffs(w00) - 1; w00 &= w00 - 1;
            const float* wv = &sw5[bit * 5];
            acc[0][0] = __fadd_rn(acc[0][0], wv[0]);
            acc[1][0] = __fadd_rn(acc[1][0], wv[1]);
            acc[2][0] = __fadd_rn(acc[2][0], wv[2]);
            acc[3][0] = __fadd_rn(acc[3][0], wv[3]);
            acc[4][0] = __fadd_rn(acc[4][0], wv[4]);
        }
        while (w01) {
            int bit = __ffs(w01) - 1; w01 &= w01 - 1;
            const float* wv = &sw5[bit * 5];
            acc[0][1] = __fadd_rn(acc[0][1], wv[0]);
            acc[1][1] = __fadd_rn(acc[1][1], wv[1]);
            acc[2][1] = __fadd_rn(acc[2][1], wv[2]);
            acc[3][1] = __fadd_rn(acc[3][1], wv[3]);
            acc[4][1] = __fadd_rn(acc[4][1], wv[4]);
        }
        while (w10) {
            int bit = __ffs(w10) - 1; w10 &= w10 - 1;
            const float* wv = &sw5[bit * 5];
            acc[0][2] = __fadd_rn(acc[0][2], wv[0]);
            acc[1][2] = __fadd_rn(acc[1][2], wv[1]);
            acc[2][2] = __fadd_rn(acc[2][2], wv[2]);
            acc[3][2] = __fadd_rn(acc[3][2], wv[3]);
            acc[4][2] = __fadd_rn(acc[4][2], wv[4]);
        }
        while (w11) {
            int bit = __ffs(w11) - 1; w11 &= w11 - 1;
            const float* wv = &sw5[bit * 5];
            acc[0][3] = __fadd_rn(acc[0][3], wv[0]);
            acc[1][3] = __fadd_rn(acc[1][3], wv[1]);
            acc[2][3] = __fadd_rn(acc[2][3], wv[2]);
            acc[3][3] = __fadd_rn(acc[3][3], wv[3]);
            acc[4][3] = __fadd_rn(acc[4][3], wv[4]);
        }

        uint32_t mask = 0u;
#pragma unroll
        for (int c = 0; c < 5; c++) {
            float m00 = m1r[c][0] + acc[c][0];
            float m01 = m1r[c][1] + acc[c][1];
            float m10 = m1r[c][2] + acc[c][2];
            float m11 = m1r[c][3] + acc[c][3];
            float f00 = (m00 > 1.f) ? 1.f : 0.f; m1r[c][0] = (m00 > 1.f) ? 0.f : m00;
            float f01 = (m01 > 1.f) ? 1.f : 0.f; m1r[c][1] = (m01 > 1.f) ? 0.f : m01;
            float f10 = (m10 > 1.f) ? 1.f : 0.f; m1r[c][2] = (m10 > 1.f) ? 0.f : m10;
            float f11 = (m11 > 1.f) ? 1.f : 0.f; m1r[c][3] = (m11 > 1.f) ? 0.f : m11;
            float ms = m1sr[c] + 0.25f * (f00 + f01 + f10 + f11);
            if (ms > 0.75f) { mask |= (1u << c); m1sr[c] = 0.f; }
            else            { m1sr[c] = ms; }
        }
        outp[(size_t)tt * (BN * 196 * 4)] = (uint8_t)mask;
    }
}

// ---------------- conv2, ALL steps: weights in smem (once), m2 AND m2s in registers ----------------
#define C2_SMEM ((13000 + 2 * 324 + 2 * 40) * 4)   // 54912 B -> 4 blocks/SM
__global__ __launch_bounds__(256, 4) void k_conv2_all() {
    extern __shared__ float dynf[];
    float*    swt    = dynf;                            // 25*500 weights (kk*520+ci*26+ch)
    uint32_t* smA    = (uint32_t*)(dynf + 13000);       // 2 x 324 mask buffers
    uint32_t* smaskA = (uint32_t*)(dynf + 13000 + 648); // 2 x 40 output masks
    int b  = blockIdx.x;
    int cb = blockIdx.y;
    int t = threadIdx.x;
    {
        const float4* src = (const float4*)(g_w2t + cb * 13000);
        float4* dst = (float4*)swt;
        for (int i = t; i < 3250; i += 256) dst[i] = src[i];
    }
    for (int i = t; i < 324; i += 256) {
        int rr = i / 18 - 2, cc = i % 18 - 2;
        uint32_t m = 0u;
        if (rr >= 0 && rr < 14 && cc >= 0 && cc < 14) {
            uint32_t w = *(const uint32_t*)&g_opmq[0][b * 196 + rr * 14 + cc][0];
            m = (w & 31u) | (((w >> 8) & 31u) << 5) | (((w >> 16) & 31u) << 10) | (((w >> 24) & 31u) << 15);
        }
        smA[i] = m;
    }
    if (t < 40) smaskA[t] = 0u;
    __syncthreads();

    float m2r[5][4];
    float m2sr[5];
#pragma unroll
    for (int u = 0; u < 5; u++) {
        m2sr[u] = 0.f;
#pragma unroll
        for (int v = 0; v < 4; v++) m2r[u][v] = 0.f;
    }

    for (int tt = 0; tt < NSTEPS; tt++) {
        int cur = tt & 1;
        uint32_t* sm    = smA + cur * 324;
        uint32_t* smask = smaskA + cur * 40;
        if (tt + 1 < NSTEPS) {
            uint32_t* smn = smA + (1 - cur) * 324;
            for (int i = t; i < 324; i += 256) {
                int rr = i / 18 - 2, cc = i % 18 - 2;
                uint32_t m = 0u;
                if (rr >= 0 && rr < 14 && cc >= 0 && cc < 14) {
                    uint32_t w = *(const uint32_t*)&g_opmq[tt + 1][b * 196 + rr * 14 + cc][0];
                    m = (w & 31u) | (((w >> 8) & 31u) << 5) | (((w >> 16) & 31u) << 10) | (((w >> 24) & 31u) << 15);
                }
                smn[i] = m;
            }
            if (t < 40) smaskA[(1 - cur) * 40 + t] = 0u;
        }

        if (t < 245) {
            int cog = t / 49, q = t % 49;
            int py = q / 7, px = q % 7;
            int r0 = 2 * py, c0 = 2 * px;
            float acc[5][4] = {};
#pragma unroll 1
            for (int ky = 0; ky < 5; ky++) {
                const uint32_t* mr0 = &sm[(r0 + ky) * 18 + c0];
                const uint32_t* mr1 = mr0 + 18;
#pragma unroll 1
                for (int kx = 0; kx < 5; kx++) {
                    uint32_t m0 = mr0[kx], m1 = mr0[kx + 1];
                    uint32_t m2w = mr1[kx], m3 = mr1[kx + 1];
                    const float* wk = &swt[(ky * 5 + kx) * 20 * 26 + cog * 5];
                    while (m0) {
                        int ci = __ffs(m0) - 1; m0 &= m0 - 1;
                        const float* w = wk + ci * 26;
                        acc[0][0] = __fadd_rn(acc[0][0], w[0]);
                        acc[1][0] = __fadd_rn(acc[1][0], w[1]);
                        acc[2][0] = __fadd_rn(acc[2][0], w[2]);
                        acc[3][0] = __fadd_rn(acc[3][0], w[3]);
                        acc[4][0] = __fadd_rn(acc[4][0], w[4]);
                    }
                    while (m1) {
                        int ci = __ffs(m1) - 1; m1 &= m1 - 1;
                        const float* w = wk + ci * 26;
                        acc[0][1] = __fadd_rn(acc[0][1], w[0]);
                        acc[1][1] = __fadd_rn(acc[1][1], w[1]);
                        acc[2][1] = __fadd_rn(acc[2][1], w[2]);
                        acc[3][1] = __fadd_rn(acc[3][1], w[3]);
                        acc[4][1] = __fadd_rn(acc[4][1], w[4]);
                    }
                    while (m2w) {
                        int ci = __ffs(m2w) - 1; m2w &= m2w - 1;
                        const float* w = wk + ci * 26;
                        acc[0][2] = __fadd_rn(acc[0][2], w[0]);
                        acc[1][2] = __fadd_rn(acc[1][2], w[1]);
                        acc[2][2] = __fadd_rn(acc[2][2], w[2]);
                        acc[3][2] = __fadd_rn(acc[3][2], w[3]);
                        acc[4][2] = __fadd_rn(acc[4][2], w[4]);
                    }
                    while (m3) {
                        int ci = __ffs(m3) - 1; m3 &= m3 - 1;
                        const float* w = wk + ci * 26;
                        acc[0][3] = __fadd_rn(acc[0][3], w[0]);
                        acc[1][3] = __fadd_rn(acc[1][3], w[1]);
                        acc[2][3] = __fadd_rn(acc[2][3], w[2]);
                        acc[3][3] = __fadd_rn(acc[3][3], w[3]);
                        acc[4][3] = __fadd_rn(acc[4][3], w[4]);
                    }
                }
            }
#pragma unroll
            for (int u = 0; u < 5; u++) {
                int colocal = cog * 5 + u;
                float m00 = m2r[u][0] + acc[u][0];
                float m01 = m2r[u][1] + acc[u][1];
                float m10 = m2r[u][2] + acc[u][2];
                float m11 = m2r[u][3] + acc[u][3];
                float f00 = (m00 > 1.f) ? 1.f : 0.f; m2r[u][0] = (m00 > 1.f) ? 0.f : m00;
                float f01 = (m01 > 1.f) ? 1.f : 0.f; m2r[u][1] = (m01 > 1.f) ? 0.f : m01;
                float f10 = (m10 > 1.f) ? 1.f : 0.f; m2r[u][2] = (m10 > 1.f) ? 0.f : m10;
                float f11 = (m11 > 1.f) ? 1.f : 0.f; m2r[u][3] = (m11 > 1.f) ? 0.f : m11;
                float ms = m2sr[u] + 0.25f * (f00 + f01 + f10 + f11);
                if (ms > 0.75f) {
                    m2sr[u] = 0.f;
                    int bit = colocal * 49 + q;
                    atomicOr(&smask[bit >> 5], 1u << (bit & 31));
                } else {
                    m2sr[u] = ms;
                }
            }
        }
        __syncthreads();
        if (t < 39) g_op2m_all[tt][b][cb][t] = smask[t];
        __syncthreads();
    }
}

// ---------------- fc0, ALL steps: mf0/tf0 in registers; sparse gather per step ----------------
__global__ __launch_bounds__(256) void k_fc0_all() {
    int b = blockIdx.x;
    __shared__ uint32_t mw[78];
    __shared__ int pfx[79];
    __shared__ uint16_t klist[2450];
    int t = threadIdx.x;
    float mf0 = 0.f, tf0 = 0.f;

    for (int tt = 0; tt < NSTEPS; tt++) {
        if (t < 39)            mw[t] = g_op2m_all[tt][b][0][t];
        else if (t < 78)       mw[t] = g_op2m_all[tt][b][1][t - 39];
        __syncthreads();
        if (t == 0) {
            int s = 0;
            for (int w = 0; w < 78; w++) { pfx[w] = s; s += __popc(mw[w]); }
            pfx[78] = s;
        }
        __syncthreads();
        if (t < 78) {
            uint32_t m = mw[t];
            int base_k = (t < 39 ? 0 : 1225) + (t < 39 ? t : t - 39) * 32;
            int o = pfx[t];
            while (m) { int j = __ffs(m) - 1; m &= m - 1; klist[o++] = (uint16_t)(base_k + j); }
        }
        __syncthreads();
        int nb = pfx[78];
        if (t < 200) {
            const float* col = g_wf0T + t;
            float acc = 0.f;
            int i = 0;
            for (; i + 8 <= nb; i += 8) {
                float v0 = __ldg(&col[(int)klist[i]     * 200]);
                float v1 = __ldg(&col[(int)klist[i + 1] * 200]);
                float v2 = __ldg(&col[(int)klist[i + 2] * 200]);
                float v3 = __ldg(&col[(int)klist[i + 3] * 200]);
                float v4 = __ldg(&col[(int)klist[i + 4] * 200]);
                float v5 = __ldg(&col[(int)klist[i + 5] * 200]);
                float v6 = __ldg(&col[(int)klist[i + 6] * 200]);
                float v7 = __ldg(&col[(int)klist[i + 7] * 200]);
                acc = __fadd_rn(acc, v0); acc = __fadd_rn(acc, v1);
                acc = __fadd_rn(acc, v2); acc = __fadd_rn(acc, v3);
                acc = __fadd_rn(acc, v4); acc = __fadd_rn(acc, v5);
                acc = __fadd_rn(acc, v6); acc = __fadd_rn(acc, v7);
            }
            for (; i < nb; i++) acc = __fadd_rn(acc, __ldg(&col[(int)klist[i] * 200]));
            float m = mf0 + acc;
            float o = (m > 1.f) ? 1.f : 0.f;
            mf0 = (m > 1.f) ? 0.f : m;
            tf0 += o;
        }
        __syncthreads();
    }
    if (t < 200) g_tf0[b * 200 + t] = tf0;
}

// ---------------- final readout: out = (Tf0 @ wf1^T) / 100 ----------------
__global__ void k_final(const float* __restrict__ wf1, float* __restrict__ out) {
    int i = blockIdx.x * blockDim.x + threadIdx.x;
    if (i >= BN * 10) return;
    int b = i / 10, j = i % 10;
    const float* tf = &g_tf0[b * 200];
    const float* w  = &wf1[j * 200];
    float s = 0.f;
#pragma unroll 8
    for (int n = 0; n < 200; n++) s = __fmaf_rn(tf[n], w[n], s);
    out[i] = s / 100.0f;
}

// ---------------- launch (single default stream) ----------------
extern "C" void kernel_launch(void* const* d_in, const int* in_sizes, int n_in,
                              void* d_out, int out_size) {
    const float* in  = (const float*)d_in[0];
    const float* w1  = (const float*)d_in[1];
    const float* w2  = (const float*)d_in[2];
    const float* wf0 = (const float*)d_in[3];
    const float* wf1 = (const float*)d_in[4];
    float* out = (float*)d_out;

    cudaFuncSetAttribute(k_conv2_all, cudaFuncAttributeMaxDynamicSharedMemorySize, C2_SMEM);

    int prep_n = 500 + 2 * 500 * 26 + 2450 * 200;
    k_prep<<<(prep_n + 255) / 256, 256>>>(w1, w2, wf0);
    int rng_warps = NSTEPS * BN * 28;
    k_rng_all<<<(rng_warps + 7) / 8, 256>>>(in);
    k_conv1_all<<<dim3(BN, 4), 224>>>();
    k_conv2_all<<<dim3(BN, 2), 256, C2_SMEM>>>();
    k_fc0_all<<<BN, 256>>>();
    k_final<<<(BN * 10 + 255) / 256, 256>>>(wf1, out);
}